// round 13
// baseline (speedup 1.0000x reference)
#include <cuda_runtime.h>
#include <cuda_bf16.h>
#include <cstdint>

// PathRaster2d R13: minimal-depth common path. 4096 blocks (1D) x 256 thr,
// tile 128x8, 1 STG.128 zero per thread issued first (no input dep), then a
// control-point-bbox reject (convex hull: all samples lie in the cp bbox;
// margin 2.5 > LINE_WIDTH covers fp rounding, only ever keeps extra tiles):
// 2 kp loads + 6 mul + balanced min/max tree + 2-axis clamp compare.
// Bbox-hit tiles run the proven per-lane sample + exact per-sample box prune
// + full 32-sample min (bit-identical to all passing rounds, rel_err 0.0).

#define CANVAS_H 2048
#define CANVAS_W 2048
#define TILE_W 128
#define TILE_H 8

__global__ void __launch_bounds__(256)
path_raster_kernel(const float* __restrict__ kp, float* __restrict__ out)
{
    const int tid = threadIdx.x;          // 0..255
    const int tx  = tid & 31;             // lane == sample index
    const int bid = blockIdx.x;
    const int x0  = (bid & 15) * TILE_W;
    const int y0  = (bid >> 4) * TILE_H;

    const int x = x0 + tx * 4;
    const int y = y0 + (tid >> 5);
    float* base = out + ((size_t)bid >> 4) * (TILE_H * CANVAS_W)
                      + (size_t)(tid >> 5) * CANVAS_W + x0 + tx * 4;

    // ---- phase 1: one unconditional zero store, no input dependency ----
    *reinterpret_cast<float4*>(base) = make_float4(0.0f, 0.0f, 0.0f, 0.0f);

    // ---- phase 2: exact reject via control-point bbox (hull property) ----
    float4 k03 = __ldg((const float4*)kp);        // y0n x0n y1n x1n
    float2 k45 = __ldg((const float2*)(kp + 4));  // y2n x2n
    float ky0 = __fmul_rn(k03.x, 2048.0f), kx0 = __fmul_rn(k03.y, 2048.0f);
    float ky1 = __fmul_rn(k03.z, 2048.0f), kx1 = __fmul_rn(k03.w, 2048.0f);
    float ky2 = __fmul_rn(k45.x, 2048.0f), kx2 = __fmul_rn(k45.y, 2048.0f);

    // balanced 2-deep min/max trees
    float ymin = fminf(fminf(ky0, ky1), ky2);
    float ymax = fmaxf(fmaxf(ky0, ky1), ky2);
    float xmin = fminf(fminf(kx0, kx1), kx2);
    float xmax = fmaxf(fmaxf(kx0, kx1), kx2);

    // clamp-distance per axis: positive => tile strictly outside by that much
    float gy = fmaxf(ymin - (float)(y0 + TILE_H - 1), (float)y0 - ymax);
    float gx = fmaxf(xmin - (float)(x0 + TILE_W - 1), (float)x0 - xmax);
    if (gy > 2.5f || gx > 2.5f)
        return;                           // ~99% of warps exit here

    // ---- phase 3: per-lane sample (ref-matched rounding), exact box prune ----
    // t_i = i * fl(1/31), endpoint forced to 1.0 (matches jnp.linspace)
    float t = (tx == 31) ? 1.0f : (float)tx * (1.0f / 31.0f);
    float u = __fsub_rn(1.0f, t);
    float b0 = __fmul_rn(u, u);
    float b1 = __fmul_rn(__fmul_rn(2.0f, t), u);
    float b2 = __fmul_rn(t, t);
    float py = __fadd_rn(__fadd_rn(__fmul_rn(b0, ky0), __fmul_rn(b1, ky1)),
                         __fmul_rn(b2, ky2));
    float px = __fadd_rn(__fadd_rn(__fmul_rn(b0, kx0), __fmul_rn(b1, kx1)),
                         __fmul_rn(b2, kx2));

    // Exact point-to-tile-box distance; squared threshold 4.5 (> 4.0) pads for
    // rounding — only ever KEEPS extra samples (dist(pixel,s) >= boxdist(s)).
    float bdy = fmaxf(fmaxf((float)y0 - py, py - (float)(y0 + TILE_H - 1)), 0.0f);
    float bdx = fmaxf(fmaxf((float)x0 - px, px - (float)(x0 + TILE_W - 1)), 0.0f);
    bool near = (bdy * bdy + bdx * bdx) < 4.5f;
    unsigned mask = __ballot_sync(0xffffffffu, near);

    if (mask == 0u) return;

    // ---- phase 4 (rare): full min for this thread's 4 pixels, overwrite ----
    const float maxd = sqrtf(2048.0f * 2048.0f + 2048.0f * 2048.0f);
    const float fy  = (float)y;
    const float fx0 = (float)x;
    const float fx1 = fx0 + 1.0f;
    const float fx2 = fx0 + 2.0f;
    const float fx3 = fx0 + 3.0f;
    float m0 = 3.4e38f, m1 = 3.4e38f, m2 = 3.4e38f, m3 = 3.4e38f;
    unsigned mm = mask;                  // warp-uniform loop
    while (mm) {
        int lane = __ffs(mm) - 1;
        mm &= mm - 1u;
        float syv = __shfl_sync(0xffffffffu, py, lane);
        float sxv = __shfl_sync(0xffffffffu, px, lane);
        float dy  = __fsub_rn(fy, syv);
        float dy2 = __fmul_rn(dy, dy);   // separate op, matches reference
        float d;
        d = __fsub_rn(fx0, sxv); m0 = fminf(m0, __fadd_rn(dy2, __fmul_rn(d, d)));
        d = __fsub_rn(fx1, sxv); m1 = fminf(m1, __fadd_rn(dy2, __fmul_rn(d, d)));
        d = __fsub_rn(fx2, sxv); m2 = fminf(m2, __fadd_rn(dy2, __fmul_rn(d, d)));
        d = __fsub_rn(fx3, sxv); m3 = fminf(m3, __fadd_rn(dy2, __fmul_rn(d, d)));
    }
    // sqrt BEFORE compare (boundary rounding identical to reference)
    float d0 = sqrtf(m0), d1 = sqrtf(m1), d2s = sqrtf(m2), d3 = sqrtf(m3);
    float4 v;
    v.x = (d0  < 2.0f) ? __fsub_rn(1.0f, __fdiv_rn(d0,  maxd)) : 0.0f;
    v.y = (d1  < 2.0f) ? __fsub_rn(1.0f, __fdiv_rn(d1,  maxd)) : 0.0f;
    v.z = (d2s < 2.0f) ? __fsub_rn(1.0f, __fdiv_rn(d2s, maxd)) : 0.0f;
    v.w = (d3  < 2.0f) ? __fsub_rn(1.0f, __fdiv_rn(d3,  maxd)) : 0.0f;
    *reinterpret_cast<float4*>(base) = v;
}

extern "C" void kernel_launch(void* const* d_in, const int* in_sizes, int n_in,
                              void* d_out, int out_size)
{
    const float* kp = (const float*)d_in[0];   // [3,2] normalized (y,x)
    float* out = (float*)d_out;                // [2048,2048] fp32

    path_raster_kernel<<<4096, 256>>>(kp, out);
}

// round 14
// speedup vs baseline: 1.0257x; 1.0257x over previous
#include <cuda_runtime.h>
#include <cuda_bf16.h>
#include <cstdint>

// PathRaster2d R14: R12's common path (zeros-first + control-point-bbox
// reject, 2D grid) at 512 threads/block: 2048 blocks, tile 128x16, still
// exactly ONE STG.128 zero per thread. Halves CTA count at constant
// per-thread work. Active path: proven per-lane sample + exact per-sample
// box prune + full 32-sample min, bit-identical to all passing rounds
// (rel_err 0.0).

#define CANVAS_H 2048
#define CANVAS_W 2048
#define TILE_W 128
#define TILE_H 16

__global__ void __launch_bounds__(512)
path_raster_kernel(const float* __restrict__ kp, float* __restrict__ out)
{
    const int tid = threadIdx.x;          // 0..511
    const int tx  = tid & 31;             // lane == sample index
    const int x0  = blockIdx.x * TILE_W;
    const int y0  = blockIdx.y * TILE_H;

    const int x = x0 + tx * 4;
    const int y = y0 + (tid >> 5);        // 16 rows, one per warp
    float* base = out + (size_t)y * CANVAS_W + x;

    // ---- phase 1: one unconditional zero store, no input dependency ----
    *reinterpret_cast<float4*>(base) = make_float4(0.0f, 0.0f, 0.0f, 0.0f);

    // ---- phase 2: exact reject via control-point bbox (hull property:
    //      every curve sample lies in the cp bbox; margin 2.5 > 2.0 covers
    //      fp rounding and only ever keeps extra tiles) ----
    float4 k03 = __ldg((const float4*)kp);        // y0n x0n y1n x1n
    float2 k45 = __ldg((const float2*)(kp + 4));  // y2n x2n
    float ky0 = __fmul_rn(k03.x, 2048.0f), kx0 = __fmul_rn(k03.y, 2048.0f);
    float ky1 = __fmul_rn(k03.z, 2048.0f), kx1 = __fmul_rn(k03.w, 2048.0f);
    float ky2 = __fmul_rn(k45.x, 2048.0f), kx2 = __fmul_rn(k45.y, 2048.0f);

    float ymin = fminf(fminf(ky0, ky1), ky2) - 2.5f;
    float ymax = fmaxf(fmaxf(ky0, ky1), ky2) + 2.5f;
    float xmin = fminf(fminf(kx0, kx1), kx2) - 2.5f;
    float xmax = fmaxf(fmaxf(kx0, kx1), kx2) + 2.5f;

    if ((float)(y0 + TILE_H - 1) < ymin || (float)y0 > ymax ||
        (float)(x0 + TILE_W - 1) < xmin || (float)x0 > xmax)
        return;                           // ~99% of warps exit here

    // ---- phase 3: per-lane sample (ref-matched rounding), exact box prune ----
    // t_i = i * fl(1/31), endpoint forced to 1.0 (matches jnp.linspace)
    float t = (tx == 31) ? 1.0f : (float)tx * (1.0f / 31.0f);
    float u = __fsub_rn(1.0f, t);
    float b0 = __fmul_rn(u, u);
    float b1 = __fmul_rn(__fmul_rn(2.0f, t), u);
    float b2 = __fmul_rn(t, t);
    float py = __fadd_rn(__fadd_rn(__fmul_rn(b0, ky0), __fmul_rn(b1, ky1)),
                         __fmul_rn(b2, ky2));
    float px = __fadd_rn(__fadd_rn(__fmul_rn(b0, kx0), __fmul_rn(b1, kx1)),
                         __fmul_rn(b2, kx2));

    // Exact point-to-tile-box distance; squared threshold 4.5 (> 4.0) pads for
    // rounding — only ever KEEPS extra samples (dist(pixel,s) >= boxdist(s)).
    float bdy = fmaxf(fmaxf((float)y0 - py, py - (float)(y0 + TILE_H - 1)), 0.0f);
    float bdx = fmaxf(fmaxf((float)x0 - px, px - (float)(x0 + TILE_W - 1)), 0.0f);
    bool near = (bdy * bdy + bdx * bdx) < 4.5f;
    unsigned mask = __ballot_sync(0xffffffffu, near);

    if (mask == 0u) return;

    // ---- phase 4 (rare): full min for this thread's 4 pixels, overwrite ----
    const float maxd = sqrtf(2048.0f * 2048.0f + 2048.0f * 2048.0f);
    const float fy  = (float)y;
    const float fx0 = (float)x;
    const float fx1 = fx0 + 1.0f;
    const float fx2 = fx0 + 2.0f;
    const float fx3 = fx0 + 3.0f;
    float m0 = 3.4e38f, m1 = 3.4e38f, m2 = 3.4e38f, m3 = 3.4e38f;
    unsigned mm = mask;                  // warp-uniform loop
    while (mm) {
        int lane = __ffs(mm) - 1;
        mm &= mm - 1u;
        float syv = __shfl_sync(0xffffffffu, py, lane);
        float sxv = __shfl_sync(0xffffffffu, px, lane);
        float dy  = __fsub_rn(fy, syv);
        float dy2 = __fmul_rn(dy, dy);   // separate op, matches reference
        float d;
        d = __fsub_rn(fx0, sxv); m0 = fminf(m0, __fadd_rn(dy2, __fmul_rn(d, d)));
        d = __fsub_rn(fx1, sxv); m1 = fminf(m1, __fadd_rn(dy2, __fmul_rn(d, d)));
        d = __fsub_rn(fx2, sxv); m2 = fminf(m2, __fadd_rn(dy2, __fmul_rn(d, d)));
        d = __fsub_rn(fx3, sxv); m3 = fminf(m3, __fadd_rn(dy2, __fmul_rn(d, d)));
    }
    // sqrt BEFORE compare (boundary rounding identical to reference)
    float d0 = sqrtf(m0), d1 = sqrtf(m1), d2s = sqrtf(m2), d3 = sqrtf(m3);
    float4 v;
    v.x = (d0  < 2.0f) ? __fsub_rn(1.0f, __fdiv_rn(d0,  maxd)) : 0.0f;
    v.y = (d1  < 2.0f) ? __fsub_rn(1.0f, __fdiv_rn(d1,  maxd)) : 0.0f;
    v.z = (d2s < 2.0f) ? __fsub_rn(1.0f, __fdiv_rn(d2s, maxd)) : 0.0f;
    v.w = (d3  < 2.0f) ? __fsub_rn(1.0f, __fdiv_rn(d3,  maxd)) : 0.0f;
    *reinterpret_cast<float4*>(base) = v;
}

extern "C" void kernel_launch(void* const* d_in, const int* in_sizes, int n_in,
                              void* d_out, int out_size)
{
    const float* kp = (const float*)d_in[0];   // [3,2] normalized (y,x)
    float* out = (float*)d_out;                // [2048,2048] fp32

    dim3 grid(CANVAS_W / TILE_W, CANVAS_H / TILE_H);  // (16, 128) = 2048 blocks
    path_raster_kernel<<<grid, 512>>>(kp, out);
}